// round 13
// baseline (speedup 1.0000x reference)
#include <cuda_runtime.h>
#include <math.h>

#define T_SEQ   4096
#define B_BATCH 4
#define C_EMB   1024
#define H_DIM   64
#define NROWS   (B_BATCH * T_SEQ)   // 16384
#define QB_CNT  (T_SEQ / 64)        // 64 query blocks per batch
#define MAXCH   16                  // 256-key chunks per q-block
#define KSPLIT  4                   // proj k-splits (256 k each)

__device__ float g_Q[NROWS * H_DIM];
__device__ float g_K[NROWS * H_DIM];
__device__ float g_V[NROWS * H_DIM];
// split-K partials: [b][qb][chunk][64 rows][64 cols] and [..][64 rows][m,l]
__device__ float g_Opart[(size_t)B_BATCH * QB_CNT * MAXCH * 64 * 64];
__device__ float g_ml[(size_t)B_BATCH * QB_CNT * MAXCH * 64 * 2];

// ---- helpers -------------------------------------------------------------
__device__ __forceinline__ unsigned f2tf(float f) {
    unsigned r;
    asm("cvt.rna.tf32.f32 %0, %1;" : "=r"(r) : "f"(f));
    return r;
}
__device__ __forceinline__ float tfbits(float f) {
    return __uint_as_float(f2tf(f));
}
__device__ __forceinline__ void mma_tf32(float* d, const unsigned* a, const unsigned* b) {
    asm("mma.sync.aligned.m16n8k8.row.col.f32.tf32.tf32.f32 "
        "{%0,%1,%2,%3}, {%4,%5,%6,%7}, {%8,%9}, {%0,%1,%2,%3};"
        : "+f"(d[0]), "+f"(d[1]), "+f"(d[2]), "+f"(d[3])
        : "r"(a[0]), "r"(a[1]), "r"(a[2]), "r"(a[3]), "r"(b[0]), "r"(b[1]));
}

// ---------------------------------------------------------------------------
// Kernel 0: zero Q/K/V accumulators (proj uses atomicAdd).
// ---------------------------------------------------------------------------
__global__ __launch_bounds__(256) void zero_qkv()
{
    size_t i = (size_t)blockIdx.x * blockDim.x + threadIdx.x;
    float4 z = make_float4(0.f, 0.f, 0.f, 0.f);
    ((float4*)g_Q)[i] = z;
    ((float4*)g_K)[i] = z;
    ((float4*)g_V)[i] = z;
}

// ---------------------------------------------------------------------------
// Kernel 1: FUSED QKV projection, split-K.
// Block = (64-row tile, ksplit of 256).  128 thr = 4 warps, warp w -> rows
// w*16..+15, 8 n-atoms x 3 outputs.  X tile shared across all three GEMMs.
// ---------------------------------------------------------------------------
__global__ __launch_bounds__(128, 3) void proj_kernel(
    const float* __restrict__ x,
    const float* __restrict__ Wq,
    const float* __restrict__ Wk,
    const float* __restrict__ Wv)
{
    __shared__ float Xs[64][36];       // [row][k]
    __shared__ float Ws[3][32][72];    // [qkv][k][n]

    const int tid  = threadIdx.x;
    const int warp = tid >> 5;
    const int lane = tid & 31;
    const int g  = lane >> 2;
    const int tg = lane & 3;
    const int row0  = blockIdx.x * 64;
    const int kbase = blockIdx.y * (C_EMB / KSPLIT);

    float acc[3][8][4];
#pragma unroll
    for (int w3 = 0; w3 < 3; w3++)
#pragma unroll
        for (int a = 0; a < 8; a++)
#pragma unroll
            for (int j = 0; j < 4; j++) acc[w3][a][j] = 0.0f;

    // X register prefetch (4 float4 per thread per chunk)
    float4 px[4];
#pragma unroll
    for (int s = 0; s < 4; s++) {
        int idx = tid + s * 128, r = idx >> 3, c4 = idx & 7;
        px[s] = *(const float4*)(x + (size_t)(row0 + r) * C_EMB + kbase + c4 * 4);
    }

    for (int c = 0; c < C_EMB / KSPLIT / 32; c++) {
        const int k0 = kbase + c * 32;
        // store prefetched X (tf32-rounded)
#pragma unroll
        for (int s = 0; s < 4; s++) {
            int idx = tid + s * 128, r = idx >> 3, c4 = idx & 7;
            float* d = &Xs[r][c4 * 4];
            d[0] = tfbits(px[s].x); d[1] = tfbits(px[s].y);
            d[2] = tfbits(px[s].z); d[3] = tfbits(px[s].w);
        }
        // W tiles (L2-resident: shared across all row-tile CTAs)
#pragma unroll
        for (int s = 0; s < 4; s++) {
            int idx = tid + s * 128, r = idx >> 4, c4 = idx & 15;
            size_t off = (size_t)(k0 + r) * H_DIM + c4 * 4;
            float4 vq = *(const float4*)(Wq + off);
            float4 vk = *(const float4*)(Wk + off);
            float4 vv = *(const float4*)(Wv + off);
            float* dq = &Ws[0][r][c4 * 4];
            dq[0] = tfbits(vq.x); dq[1] = tfbits(vq.y);
            dq[2] = tfbits(vq.z); dq[3] = tfbits(vq.w);
            float* dk = &Ws[1][r][c4 * 4];
            dk[0] = tfbits(vk.x); dk[1] = tfbits(vk.y);
            dk[2] = tfbits(vk.z); dk[3] = tfbits(vk.w);
            float* dv = &Ws[2][r][c4 * 4];
            dv[0] = tfbits(vv.x); dv[1] = tfbits(vv.y);
            dv[2] = tfbits(vv.z); dv[3] = tfbits(vv.w);
        }
        __syncthreads();

        // prefetch next X chunk while MMAs run
        if (c + 1 < C_EMB / KSPLIT / 32) {
            int kn = k0 + 32;
#pragma unroll
            for (int s = 0; s < 4; s++) {
                int idx = tid + s * 128, r = idx >> 3, c4 = idx & 7;
                px[s] = *(const float4*)(x + (size_t)(row0 + r) * C_EMB + kn + c4 * 4);
            }
        }

#pragma unroll
        for (int kc = 0; kc < 32; kc += 8) {
            unsigned a[4];
            a[0] = __float_as_uint(Xs[warp * 16 + g    ][kc + tg    ]);
            a[1] = __float_as_uint(Xs[warp * 16 + g + 8][kc + tg    ]);
            a[2] = __float_as_uint(Xs[warp * 16 + g    ][kc + tg + 4]);
            a[3] = __float_as_uint(Xs[warp * 16 + g + 8][kc + tg + 4]);
#pragma unroll
            for (int w3 = 0; w3 < 3; w3++)
#pragma unroll
                for (int at = 0; at < 8; at++) {
                    unsigned b[2];
                    b[0] = __float_as_uint(Ws[w3][kc + tg    ][at * 8 + g]);
                    b[1] = __float_as_uint(Ws[w3][kc + tg + 4][at * 8 + g]);
                    mma_tf32(acc[w3][at], a, b);
                }
        }
        __syncthreads();
    }

    // accumulate partials into globals (zeroed beforehand)
    const int r0 = row0 + warp * 16 + g;
    float* outs[3] = { g_Q, g_K, g_V };
#pragma unroll
    for (int w3 = 0; w3 < 3; w3++) {
        float* outp = outs[w3];
#pragma unroll
        for (int at = 0; at < 8; at++) {
            int cc = at * 8 + tg * 2;
            atomicAdd(&outp[(size_t)r0 * H_DIM + cc],           acc[w3][at][0]);
            atomicAdd(&outp[(size_t)r0 * H_DIM + cc + 1],       acc[w3][at][1]);
            atomicAdd(&outp[(size_t)(r0 + 8) * H_DIM + cc],     acc[w3][at][2]);
            atomicAdd(&outp[(size_t)(r0 + 8) * H_DIM + cc + 1], acc[w3][at][3]);
        }
    }
}

// ---------------------------------------------------------------------------
// Kernel 2: split-K flash partial.  CTA = (chunk of 256 keys, qb, b).
// Q fragments register-resident; K/V double-buffered; ONE barrier per tile.
// ---------------------------------------------------------------------------
__global__ __launch_bounds__(128) void flash_part_kernel()
{
    const int chunk = blockIdx.x;
    const int qb    = (QB_CNT - 1) - blockIdx.y;   // heavy blocks first
    const int b     = blockIdx.z;
    if (chunk * 4 > qb) return;                    // beyond causal limit

    const int row0 = qb * 64;
    const int nkt  = min(8, (row0 + 64 - chunk * 256 + 31) / 32);

    const float* Qp = g_Q + (size_t)b * T_SEQ * H_DIM;
    const float* Kp = g_K + (size_t)b * T_SEQ * H_DIM;
    const float* Vp = g_V + (size_t)b * T_SEQ * H_DIM;

    __shared__ float Ks[2][32][68];   // double-buffered K (also Q staging)
    __shared__ float Vs[2][32][72];   // double-buffered V
    __shared__ float Ps[64][36];

    const int tid  = threadIdx.x;
    const int warp = tid >> 5;
    const int lane = tid & 31;
    const int g  = lane >> 2;
    const int tg = lane & 3;

    // ---- stage Q through Ks, extract a-frags to registers ----
    for (int i = tid; i < 1024; i += 128) {
        int r = i >> 4, c4 = i & 15;
        float4 v = *(const float4*)(Qp + (size_t)(row0 + r) * H_DIM + c4 * 4);
        float* dst = &Ks[r >> 5][r & 31][c4 * 4];
        dst[0] = tfbits(v.x); dst[1] = tfbits(v.y);
        dst[2] = tfbits(v.z); dst[3] = tfbits(v.w);
    }
    __syncthreads();

    unsigned qa[8][4];
    {
        const int r0 = warp * 16 + g, r1 = r0 + 8;
#pragma unroll
        for (int kc8 = 0; kc8 < 8; kc8++) {
            int kc = kc8 * 8;
            qa[kc8][0] = __float_as_uint(Ks[r0 >> 5][r0 & 31][kc + tg    ]);
            qa[kc8][1] = __float_as_uint(Ks[r1 >> 5][r1 & 31][kc + tg    ]);
            qa[kc8][2] = __float_as_uint(Ks[r0 >> 5][r0 & 31][kc + tg + 4]);
            qa[kc8][3] = __float_as_uint(Ks[r1 >> 5][r1 & 31][kc + tg + 4]);
        }
    }
    __syncthreads();   // all frags extracted before Ks reused for K tiles

    float o[8][4];
#pragma unroll
    for (int a = 0; a < 8; a++)
#pragma unroll
        for (int j = 0; j < 4; j++) o[a][j] = 0.0f;
    float m0 = -1e30f, m1 = -1e30f, l0 = 0.0f, l1 = 0.0f;

    const int r0g = row0 + warp * 16 + g;
    const int r1g = r0g + 8;

    const int ld_r  = tid >> 4;          // 0..7
    const int ld_c4 = tid & 15;          // 0..15

    float4 pk[4], pv[4];
    // prefetch + store tile 0 into stage 0
    {
        const int key0 = chunk * 256;
#pragma unroll
        for (int s = 0; s < 4; s++) {
            int r = ld_r + s * 8;
            pk[s] = *(const float4*)(Kp + (size_t)(key0 + r) * H_DIM + ld_c4 * 4);
            pv[s] = *(const float4*)(Vp + (size_t)(key0 + r) * H_DIM + ld_c4 * 4);
        }
#pragma unroll
        for (int s = 0; s < 4; s++) {
            int r = ld_r + s * 8;
            float* kd = &Ks[0][r][ld_c4 * 4];
            kd[0] = tfbits(pk[s].x); kd[1] = tfbits(pk[s].y);
            kd[2] = tfbits(pk[s].z); kd[3] = tfbits(pk[s].w);
            float* vd = &Vs[0][r][ld_c4 * 4];
            vd[0] = tfbits(pv[s].x); vd[1] = tfbits(pv[s].y);
            vd[2] = tfbits(pv[s].z); vd[3] = tfbits(pv[s].w);
        }
    }

    for (int kb = 0; kb < nkt; kb++) {
        const int cur  = kb & 1;
        const int key0 = chunk * 256 + kb * 32;
        __syncthreads();

        if (kb + 1 < nkt) {
            const int keyn = key0 + 32;
#pragma unroll
            for (int s = 0; s < 4; s++) {
                int r = ld_r + s * 8;
                pk[s] = *(const float4*)(Kp + (size_t)(keyn + r) * H_DIM + ld_c4 * 4);
                pv[s] = *(const float4*)(Vp + (size_t)(keyn + r) * H_DIM + ld_c4 * 4);
            }
        }

        // ---- S = Q K^T ----
        float s[4][4];
#pragma unroll
        for (int a = 0; a < 4; a++)
#pragma unroll
            for (int j = 0; j < 4; j++) s[a][j] = 0.0f;

#pragma unroll
        for (int kc8 = 0; kc8 < 8; kc8++) {
            int kc = kc8 * 8;
#pragma unroll
            for (int at = 0; at < 4; at++) {
                unsigned bfr[2];
                bfr[0] = __float_as_uint(Ks[cur][at * 8 + g][kc + tg    ]);
                bfr[1] = __float_as_uint(Ks[cur][at * 8 + g][kc + tg + 4]);
                mma_tf32(s[at], qa[kc8], bfr);
            }
        }

        // ---- scale + causal mask ----
        const bool diag = (key0 + 31 > row0);
#pragma unroll
        for (int at = 0; at < 4; at++) {
            int c0 = key0 + at * 8 + tg * 2;
            s[at][0] *= 0.125f; s[at][1] *= 0.125f;
            s[at][2] *= 0.125f; s[at][3] *= 0.125f;
            if (diag) {
                if (c0     > r0g) s[at][0] = -1e30f;
                if (c0 + 1 > r0g) s[at][1] = -1e30f;
                if (c0     > r1g) s[at][2] = -1e30f;
                if (c0 + 1 > r1g) s[at][3] = -1e30f;
            }
        }

        // ---- online softmax ----
        float tm0 = -1e30f, tm1 = -1e30f;
#pragma unroll
        for (int at = 0; at < 4; at++) {
            tm0 = fmaxf(tm0, fmaxf(s[at][0], s[at][1]));
            tm1 = fmaxf(tm1, fmaxf(s[at][2], s[at][3]));
        }
        tm0 = fmaxf(tm0, __shfl_xor_sync(0xffffffffu, tm0, 1));
        tm0 = fmaxf(tm0, __shfl_xor_sync(0xffffffffu, tm0, 2));
        tm1 = fmaxf(tm1, __shfl_xor_sync(0xffffffffu, tm1, 1));
        tm1 = fmaxf(tm1, __shfl_xor_sync(0xffffffffu, tm1, 2));

        float nm0 = fmaxf(m0, tm0), nm1 = fmaxf(m1, tm1);
        float al0 = __expf(m0 - nm0), al1 = __expf(m1 - nm1);
        m0 = nm0; m1 = nm1;

        float tl0 = 0.0f, tl1 = 0.0f;
#pragma unroll
        for (int at = 0; at < 4; at++) {
            s[at][0] = __expf(s[at][0] - nm0);
            s[at][1] = __expf(s[at][1] - nm0);
            s[at][2] = __expf(s[at][2] - nm1);
            s[at][3] = __expf(s[at][3] - nm1);
            tl0 += s[at][0] + s[at][1];
            tl1 += s[at][2] + s[at][3];
        }
        tl0 += __shfl_xor_sync(0xffffffffu, tl0, 1);
        tl0 += __shfl_xor_sync(0xffffffffu, tl0, 2);
        tl1 += __shfl_xor_sync(0xffffffffu, tl1, 1);
        tl1 += __shfl_xor_sync(0xffffffffu, tl1, 2);
        l0 = l0 * al0 + tl0;
        l1 = l1 * al1 + tl1;

#pragma unroll
        for (int at = 0; at < 8; at++) {
            o[at][0] *= al0; o[at][1] *= al0;
            o[at][2] *= al1; o[at][3] *= al1;
        }

#pragma unroll
        for (int at = 0; at < 4; at++) {
            int c = at * 8 + tg * 2;
            Ps[warp * 16 + g    ][c    ] = tfbits(s[at][0]);
            Ps[warp * 16 + g    ][c + 1] = tfbits(s[at][1]);
            Ps[warp * 16 + g + 8][c    ] = tfbits(s[at][2]);
            Ps[warp * 16 + g + 8][c + 1] = tfbits(s[at][3]);
        }
        __syncwarp();

        // ---- O += P V ----
#pragma unroll
        for (int kc = 0; kc < 32; kc += 8) {
            unsigned a[4];
            a[0] = __float_as_uint(Ps[warp * 16 + g    ][kc + tg    ]);
            a[1] = __float_as_uint(Ps[warp * 16 + g + 8][kc + tg    ]);
            a[2] = __float_as_uint(Ps[warp * 16 + g    ][kc + tg + 4]);
            a[3] = __float_as_uint(Ps[warp * 16 + g + 8][kc + tg + 4]);
#pragma unroll
            for (int at = 0; at < 8; at++) {
                unsigned bfr[2];
                bfr[0] = __float_as_uint(Vs[cur][kc + tg    ][at * 8 + g]);
                bfr[1] = __float_as_uint(Vs[cur][kc + tg + 4][at * 8 + g]);
                mma_tf32(o[at], a, bfr);
            }
        }

        if (kb + 1 < nkt) {
            const int nxt = 1 - cur;
#pragma unroll
            for (int s = 0; s < 4; s++) {
                int r = ld_r + s * 8;
                float* kd = &Ks[nxt][r][ld_c4 * 4];
                kd[0] = tfbits(pk[s].x); kd[1] = tfbits(pk[s].y);
                kd[2] = tfbits(pk[s].z); kd[3] = tfbits(pk[s].w);
                float* vd = &Vs[nxt][r][ld_c4 * 4];
                vd[0] = tfbits(pv[s].x); vd[1] = tfbits(pv[s].y);
                vd[2] = tfbits(pv[s].z); vd[3] = tfbits(pv[s].w);
            }
        }
    }

    // ---- write partial (unnormalized O, m, l) ----
    const size_t pidx = ((size_t)(b * QB_CNT + qb) * MAXCH + chunk);
    float* Op = g_Opart + pidx * 64 * 64;
    float* mlp = g_ml + pidx * 64 * 2;

    const int lr0 = warp * 16 + g;
#pragma unroll
    for (int at = 0; at < 8; at++) {
        int c = at * 8 + tg * 2;
        *(float2*)(Op + (size_t)lr0 * 64 + c)       = make_float2(o[at][0], o[at][1]);
        *(float2*)(Op + (size_t)(lr0 + 8) * 64 + c) = make_float2(o[at][2], o[at][3]);
    }
    if (tg == 0) {
        mlp[lr0 * 2 + 0] = m0;  mlp[lr0 * 2 + 1] = l0;
        mlp[(lr0 + 8) * 2 + 0] = m1;  mlp[(lr0 + 8) * 2 + 1] = l1;
    }
}

// ---------------------------------------------------------------------------
// Kernel 3: combine partials.  Block (64 rows, 16 col-segments of 4).
// Per-row weights precomputed once into smem; accumulate loop unrolled.
// ---------------------------------------------------------------------------
__global__ __launch_bounds__(1024) void combine_kernel(float* __restrict__ out)
{
    const int qb = blockIdx.x;
    const int b  = blockIdx.y;
    const int row = threadIdx.x;       // 0..63
    const int cs  = threadIdx.y;       // 0..15
    const int nc  = qb / 4 + 1;

    const size_t base = (size_t)(b * QB_CNT + qb) * MAXCH;

    __shared__ float wsm[MAXCH][64];
    __shared__ float Linv[64];

    if (cs == 0) {
        float M = -1e30f;
        for (int c = 0; c < nc; c++)
            M = fmaxf(M, g_ml[(base + c) * 128 + row * 2 + 0]);
        float L = 0.0f;
        for (int c = 0; c < nc; c++) {
            float m = g_ml[(base + c) * 128 + row * 2 + 0];
            float l = g_ml[(base + c) * 128 + row * 2 + 1];
            float w = __expf(m - M);
            wsm[c][row] = w;
            L += w * l;
        }
        Linv[row] = 1.0f / L;
    }
    __syncthreads();

    float acc0 = 0.f, acc1 = 0.f, acc2 = 0.f, acc3 = 0.f;
    const float* Ob = g_Opart + base * 4096 + (size_t)row * 64 + cs * 4;
#pragma unroll 4
    for (int c = 0; c < nc; c++) {
        float w = wsm[c][row];
        float4 v = *(const float4*)(Ob + (size_t)c * 4096);
        acc0 += w * v.x; acc1 += w * v.y; acc2 += w * v.z; acc3 += w * v.w;
    }

    float inv = Linv[row];
    float* op = out + (size_t)b * T_SEQ * H_DIM + (size_t)(qb * 64 + row) * H_DIM + cs * 4;
    *(float4*)op = make_float4(acc0 * inv, acc1 * inv, acc2 * inv, acc3 * inv);
}

// ---------------------------------------------------------------------------
extern "C" void kernel_launch(void* const* d_in, const int* in_sizes, int n_in,
                              void* d_out, int out_size)
{
    const float* x  = (const float*)d_in[0];
    const float* Wq = (const float*)d_in[1];
    const float* Wk = (const float*)d_in[2];
    const float* Wv = (const float*)d_in[3];
    float* out = (float*)d_out;

    zero_qkv<<<NROWS * H_DIM / 4 / 256, 256>>>();

    dim3 g1(NROWS / 64, KSPLIT);
    proj_kernel<<<g1, 128>>>(x, Wq, Wk, Wv);

    dim3 g2(MAXCH, QB_CNT, B_BATCH);
    flash_part_kernel<<<g2, 128>>>();

    dim3 g3(QB_CNT, B_BATCH);
    combine_kernel<<<g3, dim3(64, 16)>>>(out);
}

// round 15
// speedup vs baseline: 1.1014x; 1.1014x over previous
#include <cuda_runtime.h>
#include <cuda_fp16.h>
#include <math.h>

#define T_SEQ   4096
#define B_BATCH 4
#define C_EMB   1024
#define H_DIM   64
#define NROWS   (B_BATCH * T_SEQ)   // 16384
#define QB_CNT  (T_SEQ / 64)        // 64 query blocks per batch
#define MAXCH   16                  // 256-key chunks per q-block
#define KSPLIT  4                   // proj k-splits (256 k each)

__device__ float g_Q[NROWS * H_DIM];
__device__ float g_K[NROWS * H_DIM];
__device__ float g_V[NROWS * H_DIM];
// split-K partials: [b][qb][chunk][64 rows][64 cols] and [..][64 rows][m,l]
__device__ float g_Opart[(size_t)B_BATCH * QB_CNT * MAXCH * 64 * 64];
__device__ float g_ml[(size_t)B_BATCH * QB_CNT * MAXCH * 64 * 2];

// ---- helpers -------------------------------------------------------------
// pack two floats into half2 bits (lo = a, hi = b)
__device__ __forceinline__ unsigned h2u(float a, float b) {
    __half2 h = __floats2half2_rn(a, b);
    return *(unsigned*)&h;
}
// D += A(16x16,row) * B(16x8,col)   f16 -> f32
__device__ __forceinline__ void mma_f16(float* d, const unsigned* a,
                                        unsigned b0, unsigned b1) {
    asm("mma.sync.aligned.m16n8k16.row.col.f32.f16.f16.f32 "
        "{%0,%1,%2,%3}, {%4,%5,%6,%7}, {%8,%9}, {%0,%1,%2,%3};"
        : "+f"(d[0]), "+f"(d[1]), "+f"(d[2]), "+f"(d[3])
        : "r"(a[0]), "r"(a[1]), "r"(a[2]), "r"(a[3]), "r"(b0), "r"(b1));
}
__device__ __forceinline__ unsigned ldu32(const __half* p) {
    return *(const unsigned*)p;
}

// ---------------------------------------------------------------------------
// Kernel 0: zero Q/K/V accumulators (proj uses atomicAdd).
// ---------------------------------------------------------------------------
__global__ __launch_bounds__(256) void zero_qkv()
{
    size_t i = (size_t)blockIdx.x * blockDim.x + threadIdx.x;
    float4 z = make_float4(0.f, 0.f, 0.f, 0.f);
    ((float4*)g_Q)[i] = z;
    ((float4*)g_K)[i] = z;
    ((float4*)g_V)[i] = z;
}

// ---------------------------------------------------------------------------
// Kernel 1: QKV projection, split-K, fp16 MMA.
// Block = (rowtile 128, ksplit of 256, output sel).  256 thr = 8 warps.
// Xs [row][k] pitch 40h;  W transposed Wt [n][k] pitch 40h.
// ---------------------------------------------------------------------------
__global__ __launch_bounds__(256) void proj_kernel(
    const float* __restrict__ x,
    const float* __restrict__ Wq,
    const float* __restrict__ Wk,
    const float* __restrict__ Wv)
{
    const float* W;
    float* outp;
    if (blockIdx.z == 0)      { W = Wq; outp = g_Q; }
    else if (blockIdx.z == 1) { W = Wk; outp = g_K; }
    else                      { W = Wv; outp = g_V; }

    __shared__ __half Xs[128][40];   // [row][k 0..31]
    __shared__ __half Wt[64][40];    // [n][k 0..31]  (transposed)

    const int tid  = threadIdx.x;
    const int warp = tid >> 5;
    const int lane = tid & 31;
    const int g  = lane >> 2;
    const int tg = lane & 3;
    const int row0  = blockIdx.x * 128;
    const int kbase = blockIdx.y * (C_EMB / KSPLIT);

    float acc[8][4];
#pragma unroll
    for (int a = 0; a < 8; a++)
#pragma unroll
        for (int j = 0; j < 4; j++) acc[a][j] = 0.0f;

    float4 px[4], pw[2];
#pragma unroll
    for (int s = 0; s < 4; s++) {
        int idx = tid + s * 256, r = idx >> 3, c4 = idx & 7;
        px[s] = *(const float4*)(x + (size_t)(row0 + r) * C_EMB + kbase + c4 * 4);
    }
#pragma unroll
    for (int s = 0; s < 2; s++) {
        int idx = tid + s * 256, r = idx >> 4, c4 = idx & 15;
        pw[s] = *(const float4*)(W + (size_t)(kbase + r) * H_DIM + c4 * 4);
    }

    for (int c = 0; c < C_EMB / KSPLIT / 32; c++) {
        // store prefetched X as half (8B per float4)
#pragma unroll
        for (int s = 0; s < 4; s++) {
            int idx = tid + s * 256, r = idx >> 3, c4 = idx & 7;
            uint2 v = make_uint2(h2u(px[s].x, px[s].y), h2u(px[s].z, px[s].w));
            *(uint2*)&Xs[r][c4 * 4] = v;
        }
        // store prefetched W transposed (scattered half stores)
#pragma unroll
        for (int s = 0; s < 2; s++) {
            int idx = tid + s * 256, r = idx >> 4, c4 = idx & 15;
            Wt[c4 * 4 + 0][r] = __float2half_rn(pw[s].x);
            Wt[c4 * 4 + 1][r] = __float2half_rn(pw[s].y);
            Wt[c4 * 4 + 2][r] = __float2half_rn(pw[s].z);
            Wt[c4 * 4 + 3][r] = __float2half_rn(pw[s].w);
        }
        __syncthreads();

        if (c + 1 < C_EMB / KSPLIT / 32) {
            int k0 = kbase + (c + 1) * 32;
#pragma unroll
            for (int s = 0; s < 4; s++) {
                int idx = tid + s * 256, r = idx >> 3, c4 = idx & 7;
                px[s] = *(const float4*)(x + (size_t)(row0 + r) * C_EMB + k0 + c4 * 4);
            }
#pragma unroll
            for (int s = 0; s < 2; s++) {
                int idx = tid + s * 256, r = idx >> 4, c4 = idx & 15;
                pw[s] = *(const float4*)(W + (size_t)(k0 + r) * H_DIM + c4 * 4);
            }
        }

#pragma unroll
        for (int kc = 0; kc < 32; kc += 16) {
            unsigned a[4];
            a[0] = ldu32(&Xs[warp * 16 + g    ][kc + 2 * tg    ]);
            a[1] = ldu32(&Xs[warp * 16 + g + 8][kc + 2 * tg    ]);
            a[2] = ldu32(&Xs[warp * 16 + g    ][kc + 2 * tg + 8]);
            a[3] = ldu32(&Xs[warp * 16 + g + 8][kc + 2 * tg + 8]);
#pragma unroll
            for (int at = 0; at < 8; at++) {
                unsigned b0 = ldu32(&Wt[at * 8 + g][kc + 2 * tg    ]);
                unsigned b1 = ldu32(&Wt[at * 8 + g][kc + 2 * tg + 8]);
                mma_f16(acc[at], a, b0, b1);
            }
        }
        __syncthreads();
    }

    const int r0 = row0 + warp * 16 + g;
#pragma unroll
    for (int at = 0; at < 8; at++) {
        int cc = at * 8 + tg * 2;
        atomicAdd(&outp[(size_t)r0 * H_DIM + cc],           acc[at][0]);
        atomicAdd(&outp[(size_t)r0 * H_DIM + cc + 1],       acc[at][1]);
        atomicAdd(&outp[(size_t)(r0 + 8) * H_DIM + cc],     acc[at][2]);
        atomicAdd(&outp[(size_t)(r0 + 8) * H_DIM + cc + 1], acc[at][3]);
    }
}

// ---------------------------------------------------------------------------
// Kernel 2: split-K flash partial, fp16 MMA.  CTA = (chunk, qb, b).
// Q frags in regs; K/V double-buffered (V transposed); one barrier per tile.
// ---------------------------------------------------------------------------
__global__ __launch_bounds__(128) void flash_part_kernel()
{
    const int chunk = blockIdx.x;
    const int qb    = (QB_CNT - 1) - blockIdx.y;   // heavy blocks first
    const int b     = blockIdx.z;
    if (chunk * 4 > qb) return;                    // beyond causal limit

    const int row0 = qb * 64;
    const int nkt  = min(8, (row0 + 64 - chunk * 256 + 31) / 32);

    const float* Qp = g_Q + (size_t)b * T_SEQ * H_DIM;
    const float* Kp = g_K + (size_t)b * T_SEQ * H_DIM;
    const float* Vp = g_V + (size_t)b * T_SEQ * H_DIM;

    __shared__ __half Ks[2][32][72];   // [key][ch]; also Q staging (64x72)
    __shared__ __half Vt[2][64][40];   // [h][key]   (transposed)
    __shared__ __half Ps[64][40];      // [row][key]

    const int tid  = threadIdx.x;
    const int warp = tid >> 5;
    const int lane = tid & 31;
    const int g  = lane >> 2;
    const int tg = lane & 3;

    // ---- stage Q through Ks (flat 64 rows), extract a-frags ----
    {
        __half* Qs = (__half*)Ks;
        for (int i = tid; i < 1024; i += 128) {
            int r = i >> 4, c4 = i & 15;
            float4 v = *(const float4*)(Qp + (size_t)(row0 + r) * H_DIM + c4 * 4);
            *(uint2*)&Qs[r * 72 + c4 * 4] =
                make_uint2(h2u(v.x, v.y), h2u(v.z, v.w));
        }
    }
    __syncthreads();

    unsigned qa[4][4];
    {
        const __half* Qs = (const __half*)Ks;
        const int r0 = warp * 16 + g, r1 = r0 + 8;
#pragma unroll
        for (int kc4 = 0; kc4 < 4; kc4++) {
            int kc = kc4 * 16;
            qa[kc4][0] = ldu32(&Qs[r0 * 72 + kc + 2 * tg    ]);
            qa[kc4][1] = ldu32(&Qs[r1 * 72 + kc + 2 * tg    ]);
            qa[kc4][2] = ldu32(&Qs[r0 * 72 + kc + 2 * tg + 8]);
            qa[kc4][3] = ldu32(&Qs[r1 * 72 + kc + 2 * tg + 8]);
        }
    }
    __syncthreads();   // frags extracted before Ks reused for K tiles

    float o[8][4];
#pragma unroll
    for (int a = 0; a < 8; a++)
#pragma unroll
        for (int j = 0; j < 4; j++) o[a][j] = 0.0f;
    float m0 = -1e30f, m1 = -1e30f, l0 = 0.0f, l1 = 0.0f;

    const int r0g = row0 + warp * 16 + g;
    const int r1g = r0g + 8;

    const int ld_r  = tid >> 4;          // 0..7
    const int ld_c4 = tid & 15;          // 0..15

    float4 pk[4], pv[4];
    // prefetch + store tile 0 into stage 0
    {
        const int key0 = chunk * 256;
#pragma unroll
        for (int s = 0; s < 4; s++) {
            int r = ld_r + s * 8;
            pk[s] = *(const float4*)(Kp + (size_t)(key0 + r) * H_DIM + ld_c4 * 4);
            pv[s] = *(const float4*)(Vp + (size_t)(key0 + r) * H_DIM + ld_c4 * 4);
        }
#pragma unroll
        for (int s = 0; s < 4; s++) {
            int r = ld_r + s * 8;
            *(uint2*)&Ks[0][r][ld_c4 * 4] =
                make_uint2(h2u(pk[s].x, pk[s].y), h2u(pk[s].z, pk[s].w));
            Vt[0][ld_c4 * 4 + 0][r] = __float2half_rn(pv[s].x);
            Vt[0][ld_c4 * 4 + 1][r] = __float2half_rn(pv[s].y);
            Vt[0][ld_c4 * 4 + 2][r] = __float2half_rn(pv[s].z);
            Vt[0][ld_c4 * 4 + 3][r] = __float2half_rn(pv[s].w);
        }
    }

    for (int kb = 0; kb < nkt; kb++) {
        const int cur  = kb & 1;
        const int key0 = chunk * 256 + kb * 32;
        __syncthreads();

        if (kb + 1 < nkt) {
            const int keyn = key0 + 32;
#pragma unroll
            for (int s = 0; s < 4; s++) {
                int r = ld_r + s * 8;
                pk[s] = *(const float4*)(Kp + (size_t)(keyn + r) * H_DIM + ld_c4 * 4);
                pv[s] = *(const float4*)(Vp + (size_t)(keyn + r) * H_DIM + ld_c4 * 4);
            }
        }

        // ---- S = Q K^T : 4 atoms x 4 k-chunks of 16 ----
        float s[4][4];
#pragma unroll
        for (int a = 0; a < 4; a++)
#pragma unroll
            for (int j = 0; j < 4; j++) s[a][j] = 0.0f;

#pragma unroll
        for (int kc4 = 0; kc4 < 4; kc4++) {
            int kc = kc4 * 16;
#pragma unroll
            for (int at = 0; at < 4; at++) {
                unsigned b0 = ldu32(&Ks[cur][at * 8 + g][kc + 2 * tg    ]);
                unsigned b1 = ldu32(&Ks[cur][at * 8 + g][kc + 2 * tg + 8]);
                mma_f16(s[at], qa[kc4], b0, b1);
            }
        }

        // ---- scale + causal mask ----
        const bool diag = (key0 + 31 > row0);
#pragma unroll
        for (int at = 0; at < 4; at++) {
            int c0 = key0 + at * 8 + tg * 2;
            s[at][0] *= 0.125f; s[at][1] *= 0.125f;
            s[at][2] *= 0.125f; s[at][3] *= 0.125f;
            if (diag) {
                if (c0     > r0g) s[at][0] = -1e30f;
                if (c0 + 1 > r0g) s[at][1] = -1e30f;
                if (c0     > r1g) s[at][2] = -1e30f;
                if (c0 + 1 > r1g) s[at][3] = -1e30f;
            }
        }

        // ---- online softmax ----
        float tm0 = -1e30f, tm1 = -1e30f;
#pragma unroll
        for (int at = 0; at < 4; at++) {
            tm0 = fmaxf(tm0, fmaxf(s[at][0], s[at][1]));
            tm1 = fmaxf(tm1, fmaxf(s[at][2], s[at][3]));
        }
        tm0 = fmaxf(tm0, __shfl_xor_sync(0xffffffffu, tm0, 1));
        tm0 = fmaxf(tm0, __shfl_xor_sync(0xffffffffu, tm0, 2));
        tm1 = fmaxf(tm1, __shfl_xor_sync(0xffffffffu, tm1, 1));
        tm1 = fmaxf(tm1, __shfl_xor_sync(0xffffffffu, tm1, 2));

        float nm0 = fmaxf(m0, tm0), nm1 = fmaxf(m1, tm1);
        float al0 = __expf(m0 - nm0), al1 = __expf(m1 - nm1);
        m0 = nm0; m1 = nm1;

        float tl0 = 0.0f, tl1 = 0.0f;
#pragma unroll
        for (int at = 0; at < 4; at++) {
            s[at][0] = __expf(s[at][0] - nm0);
            s[at][1] = __expf(s[at][1] - nm0);
            s[at][2] = __expf(s[at][2] - nm1);
            s[at][3] = __expf(s[at][3] - nm1);
            tl0 += s[at][0] + s[at][1];
            tl1 += s[at][2] + s[at][3];
        }
        tl0 += __shfl_xor_sync(0xffffffffu, tl0, 1);
        tl0 += __shfl_xor_sync(0xffffffffu, tl0, 2);
        tl1 += __shfl_xor_sync(0xffffffffu, tl1, 1);
        tl1 += __shfl_xor_sync(0xffffffffu, tl1, 2);
        l0 = l0 * al0 + tl0;
        l1 = l1 * al1 + tl1;

#pragma unroll
        for (int at = 0; at < 8; at++) {
            o[at][0] *= al0; o[at][1] *= al0;
            o[at][2] *= al1; o[at][3] *= al1;
        }

        // stage P as half2 pairs (warp-local rows)
#pragma unroll
        for (int at = 0; at < 4; at++) {
            int c = at * 8 + 2 * tg;
            *(unsigned*)&Ps[warp * 16 + g    ][c] = h2u(s[at][0], s[at][1]);
            *(unsigned*)&Ps[warp * 16 + g + 8][c] = h2u(s[at][2], s[at][3]);
        }
        __syncwarp();

        // ---- O += P V : 8 atoms x 2 k-chunks of 16 ----
#pragma unroll
        for (int kc = 0; kc < 32; kc += 16) {
            unsigned a[4];
            a[0] = ldu32(&Ps[warp * 16 + g    ][kc + 2 * tg    ]);
            a[1] = ldu32(&Ps[warp * 16 + g + 8][kc + 2 * tg    ]);
            a[2] = ldu32(&Ps[warp * 16 + g    ][kc + 2 * tg + 8]);
            a[3] = ldu32(&Ps[warp * 16 + g + 8][kc + 2 * tg + 8]);
#pragma unroll
            for (int at = 0; at < 8; at++) {
                unsigned b0 = ldu32(&Vt[cur][at * 8 + g][kc + 2 * tg    ]);
                unsigned b1 = ldu32(&Vt[cur][at * 8 + g][kc + 2 * tg + 8]);
                mma_f16(o[at], a, b0, b1);
            }
        }

        // store prefetched tile into the other stage
        if (kb + 1 < nkt) {
            const int nxt = 1 - cur;
#pragma unroll
            for (int s = 0; s < 4; s++) {
                int r = ld_r + s * 8;
                *(uint2*)&Ks[nxt][r][ld_c4 * 4] =
                    make_uint2(h2u(pk[s].x, pk[s].y), h2u(pk[s].z, pk[s].w));
                Vt[nxt][ld_c4 * 4 + 0][r] = __float2half_rn(pv[s].x);
                Vt[nxt][ld_c4 * 4 + 1][r] = __float2half_rn(pv[s].y);
                Vt[nxt][ld_c4 * 4 + 2][r] = __float2half_rn(pv[s].z);
                Vt[nxt][ld_c4 * 4 + 3][r] = __float2half_rn(pv[s].w);
            }
        }
    }

    // ---- write partial (unnormalized O, m, l) ----
    const size_t pidx = ((size_t)(b * QB_CNT + qb) * MAXCH + chunk);
    float* Op = g_Opart + pidx * 64 * 64;
    float* mlp = g_ml + pidx * 64 * 2;

    const int lr0 = warp * 16 + g;
#pragma unroll
    for (int at = 0; at < 8; at++) {
        int c = at * 8 + tg * 2;
        *(float2*)(Op + (size_t)lr0 * 64 + c)       = make_float2(o[at][0], o[at][1]);
        *(float2*)(Op + (size_t)(lr0 + 8) * 64 + c) = make_float2(o[at][2], o[at][3]);
    }
    if (tg == 0) {
        mlp[lr0 * 2 + 0] = m0;  mlp[lr0 * 2 + 1] = l0;
        mlp[(lr0 + 8) * 2 + 0] = m1;  mlp[(lr0 + 8) * 2 + 1] = l1;
    }
}

// ---------------------------------------------------------------------------
// Kernel 3: combine partials.  Block (64 rows, 16 col-segments of 4).
// ---------------------------------------------------------------------------
__global__ __launch_bounds__(1024) void combine_kernel(float* __restrict__ out)
{
    const int qb = blockIdx.x;
    const int b  = blockIdx.y;
    const int row = threadIdx.x;       // 0..63
    const int cs  = threadIdx.y;       // 0..15
    const int nc  = qb / 4 + 1;

    const size_t base = (size_t)(b * QB_CNT + qb) * MAXCH;

    __shared__ float wsm[MAXCH][64];
    __shared__ float Linv[64];

    if (cs == 0) {
        float M = -1e30f;
        for (int c = 0; c < nc; c++)
            M = fmaxf(M, g_ml[(base + c) * 128 + row * 2 + 0]);
        float L = 0.0f;
        for (int c = 0; c < nc; c++) {
            float m = g_ml[(base + c) * 128 + row * 2 + 0];
            float l = g_ml[(base + c) * 128 + row * 2 + 1];
            float w = __expf(m - M);
            wsm[c][row] = w;
            L += w * l;
        }
        Linv[row] = 1.0f / L;
    }
    __syncthreads();

    float acc0 = 0.f, acc1 = 0.f, acc2 = 0.f, acc3 = 0.f;
    const float* Ob = g_Opart + base * 4096 + (size_t)row * 64 + cs * 4;
#pragma unroll 4
    for (int c = 0; c < nc; c++) {
        float w = wsm[c][row];
        float4 v = *(const float4*)(Ob + (size_t)c * 4096);
        acc0 += w * v.x; acc1 += w * v.y; acc2 += w * v.z; acc3 += w * v.w;
    }

    float inv = Linv[row];
    float* op = out + (size_t)b * T_SEQ * H_DIM + (size_t)(qb * 64 + row) * H_DIM + cs * 4;
    *(float4*)op = make_float4(acc0 * inv, acc1 * inv, acc2 * inv, acc3 * inv);
}

// ---------------------------------------------------------------------------
extern "C" void kernel_launch(void* const* d_in, const int* in_sizes, int n_in,
                              void* d_out, int out_size)
{
    const float* x  = (const float*)d_in[0];
    const float* Wq = (const float*)d_in[1];
    const float* Wk = (const float*)d_in[2];
    const float* Wv = (const float*)d_in[3];
    float* out = (float*)d_out;

    zero_qkv<<<NROWS * H_DIM / 4 / 256, 256>>>();

    dim3 g1(NROWS / 128, KSPLIT, 3);
    proj_kernel<<<g1, 256>>>(x, Wq, Wk, Wv);

    dim3 g2(MAXCH, QB_CNT, B_BATCH);
    flash_part_kernel<<<g2, 128>>>();

    dim3 g3(QB_CNT, B_BATCH);
    combine_kernel<<<g3, dim3(64, 16)>>>(out);
}

// round 16
// speedup vs baseline: 1.1365x; 1.0318x over previous
#include <cuda_runtime.h>
#include <cuda_fp16.h>
#include <math.h>

#define T_SEQ   4096
#define B_BATCH 4
#define C_EMB   1024
#define H_DIM   64
#define NROWS   (B_BATCH * T_SEQ)   // 16384
#define QB_CNT  (T_SEQ / 64)        // 64 query blocks per batch
#define MAXCH   16                  // 256-key chunks per q-block
#define KSPLIT  4                   // proj k-splits (256 k each)

__device__ float g_Q[NROWS * H_DIM];
__device__ float g_K[NROWS * H_DIM];
__device__ float g_V[NROWS * H_DIM];
// split-K partials: [b][qb][chunk][64 rows][64 cols] and [..][64 rows][m,l]
__device__ float g_Opart[(size_t)B_BATCH * QB_CNT * MAXCH * 64 * 64];
__device__ float g_ml[(size_t)B_BATCH * QB_CNT * MAXCH * 64 * 2];

// ---- helpers -------------------------------------------------------------
__device__ __forceinline__ unsigned h2u(float a, float b) {
    __half2 h = __floats2half2_rn(a, b);
    return *(unsigned*)&h;
}
// D += A(16x16,row) * B(16x8,col)   f16 -> f32
__device__ __forceinline__ void mma_f16(float* d, const unsigned* a,
                                        unsigned b0, unsigned b1) {
    asm("mma.sync.aligned.m16n8k16.row.col.f32.f16.f16.f32 "
        "{%0,%1,%2,%3}, {%4,%5,%6,%7}, {%8,%9}, {%0,%1,%2,%3};"
        : "+f"(d[0]), "+f"(d[1]), "+f"(d[2]), "+f"(d[3])
        : "r"(a[0]), "r"(a[1]), "r"(a[2]), "r"(a[3]), "r"(b0), "r"(b1));
}
__device__ __forceinline__ unsigned ldu32(const __half* p) {
    return *(const unsigned*)p;
}

// ---------------------------------------------------------------------------
// Kernel 0: zero Q/K/V accumulators (proj uses atomicAdd).
// ---------------------------------------------------------------------------
__global__ __launch_bounds__(256) void zero_qkv()
{
    size_t i = (size_t)blockIdx.x * blockDim.x + threadIdx.x;
    float4 z = make_float4(0.f, 0.f, 0.f, 0.f);
    ((float4*)g_Q)[i] = z;
    ((float4*)g_K)[i] = z;
    ((float4*)g_V)[i] = z;
}

// ---------------------------------------------------------------------------
// Kernel 1: QKV projection, split-K, fp16 MMA (unchanged from R15).
// ---------------------------------------------------------------------------
__global__ __launch_bounds__(256) void proj_kernel(
    const float* __restrict__ x,
    const float* __restrict__ Wq,
    const float* __restrict__ Wk,
    const float* __restrict__ Wv)
{
    const float* W;
    float* outp;
    if (blockIdx.z == 0)      { W = Wq; outp = g_Q; }
    else if (blockIdx.z == 1) { W = Wk; outp = g_K; }
    else                      { W = Wv; outp = g_V; }

    __shared__ __half Xs[128][40];   // [row][k 0..31]
    __shared__ __half Wt[64][40];    // [n][k 0..31]  (transposed)

    const int tid  = threadIdx.x;
    const int warp = tid >> 5;
    const int lane = tid & 31;
    const int g  = lane >> 2;
    const int tg = lane & 3;
    const int row0  = blockIdx.x * 128;
    const int kbase = blockIdx.y * (C_EMB / KSPLIT);

    float acc[8][4];
#pragma unroll
    for (int a = 0; a < 8; a++)
#pragma unroll
        for (int j = 0; j < 4; j++) acc[a][j] = 0.0f;

    float4 px[4], pw[2];
#pragma unroll
    for (int s = 0; s < 4; s++) {
        int idx = tid + s * 256, r = idx >> 3, c4 = idx & 7;
        px[s] = *(const float4*)(x + (size_t)(row0 + r) * C_EMB + kbase + c4 * 4);
    }
#pragma unroll
    for (int s = 0; s < 2; s++) {
        int idx = tid + s * 256, r = idx >> 4, c4 = idx & 15;
        pw[s] = *(const float4*)(W + (size_t)(kbase + r) * H_DIM + c4 * 4);
    }

    for (int c = 0; c < C_EMB / KSPLIT / 32; c++) {
#pragma unroll
        for (int s = 0; s < 4; s++) {
            int idx = tid + s * 256, r = idx >> 3, c4 = idx & 7;
            uint2 v = make_uint2(h2u(px[s].x, px[s].y), h2u(px[s].z, px[s].w));
            *(uint2*)&Xs[r][c4 * 4] = v;
        }
#pragma unroll
        for (int s = 0; s < 2; s++) {
            int idx = tid + s * 256, r = idx >> 4, c4 = idx & 15;
            Wt[c4 * 4 + 0][r] = __float2half_rn(pw[s].x);
            Wt[c4 * 4 + 1][r] = __float2half_rn(pw[s].y);
            Wt[c4 * 4 + 2][r] = __float2half_rn(pw[s].z);
            Wt[c4 * 4 + 3][r] = __float2half_rn(pw[s].w);
        }
        __syncthreads();

        if (c + 1 < C_EMB / KSPLIT / 32) {
            int k0 = kbase + (c + 1) * 32;
#pragma unroll
            for (int s = 0; s < 4; s++) {
                int idx = tid + s * 256, r = idx >> 3, c4 = idx & 7;
                px[s] = *(const float4*)(x + (size_t)(row0 + r) * C_EMB + k0 + c4 * 4);
            }
#pragma unroll
            for (int s = 0; s < 2; s++) {
                int idx = tid + s * 256, r = idx >> 4, c4 = idx & 15;
                pw[s] = *(const float4*)(W + (size_t)(k0 + r) * H_DIM + c4 * 4);
            }
        }

#pragma unroll
        for (int kc = 0; kc < 32; kc += 16) {
            unsigned a[4];
            a[0] = ldu32(&Xs[warp * 16 + g    ][kc + 2 * tg    ]);
            a[1] = ldu32(&Xs[warp * 16 + g + 8][kc + 2 * tg    ]);
            a[2] = ldu32(&Xs[warp * 16 + g    ][kc + 2 * tg + 8]);
            a[3] = ldu32(&Xs[warp * 16 + g + 8][kc + 2 * tg + 8]);
#pragma unroll
            for (int at = 0; at < 8; at++) {
                unsigned b0 = ldu32(&Wt[at * 8 + g][kc + 2 * tg    ]);
                unsigned b1 = ldu32(&Wt[at * 8 + g][kc + 2 * tg + 8]);
                mma_f16(acc[at], a, b0, b1);
            }
        }
        __syncthreads();
    }

    const int r0 = row0 + warp * 16 + g;
#pragma unroll
    for (int at = 0; at < 8; at++) {
        int cc = at * 8 + tg * 2;
        atomicAdd(&outp[(size_t)r0 * H_DIM + cc],           acc[at][0]);
        atomicAdd(&outp[(size_t)r0 * H_DIM + cc + 1],       acc[at][1]);
        atomicAdd(&outp[(size_t)(r0 + 8) * H_DIM + cc],     acc[at][2]);
        atomicAdd(&outp[(size_t)(r0 + 8) * H_DIM + cc + 1], acc[at][3]);
    }
}

// ---------------------------------------------------------------------------
// Kernel 2: split-K flash partial, fp16 MMA, BN=64 key tiles.
// One barrier per 64 keys; staggered K/V prefetch; Vt pitch 74 (2-way stores).
// ---------------------------------------------------------------------------
__global__ __launch_bounds__(128, 3) void flash_part_kernel()
{
    const int chunk = blockIdx.x;
    const int qb    = (QB_CNT - 1) - blockIdx.y;   // heavy blocks first
    const int b     = blockIdx.z;
    if (chunk * 4 > qb) return;                    // beyond causal limit

    const int row0 = qb * 64;
    const int nkt  = min(4, qb + 1 - chunk * 4);   // 64-key tiles (exact)

    const float* Qp = g_Q + (size_t)b * T_SEQ * H_DIM;
    const float* Kp = g_K + (size_t)b * T_SEQ * H_DIM;
    const float* Vp = g_V + (size_t)b * T_SEQ * H_DIM;

    __shared__ __half Ks[2][64][72];   // [key][ch]; stage0+1 also Q staging
    __shared__ __half Vt[2][64][74];   // [h][key]  pitch 74
    __shared__ __half Ps[64][72];      // [row][key]

    const int tid  = threadIdx.x;
    const int warp = tid >> 5;
    const int lane = tid & 31;
    const int g  = lane >> 2;
    const int tg = lane & 3;

    // ---- stage Q through Ks flat, extract a-frags ----
    {
        __half* Qs = (__half*)Ks;
        for (int i = tid; i < 1024; i += 128) {
            int r = i >> 4, c4 = i & 15;
            float4 v = *(const float4*)(Qp + (size_t)(row0 + r) * H_DIM + c4 * 4);
            *(uint2*)&Qs[r * 72 + c4 * 4] =
                make_uint2(h2u(v.x, v.y), h2u(v.z, v.w));
        }
    }
    __syncthreads();

    unsigned qa[4][4];
    {
        const __half* Qs = (const __half*)Ks;
        const int r0 = warp * 16 + g, r1 = r0 + 8;
#pragma unroll
        for (int kc4 = 0; kc4 < 4; kc4++) {
            int kc = kc4 * 16;
            qa[kc4][0] = ldu32(&Qs[r0 * 72 + kc + 2 * tg    ]);
            qa[kc4][1] = ldu32(&Qs[r1 * 72 + kc + 2 * tg    ]);
            qa[kc4][2] = ldu32(&Qs[r0 * 72 + kc + 2 * tg + 8]);
            qa[kc4][3] = ldu32(&Qs[r1 * 72 + kc + 2 * tg + 8]);
        }
    }
    __syncthreads();   // frags extracted before Ks reused for K tiles

    float o[8][4];
#pragma unroll
    for (int a = 0; a < 8; a++)
#pragma unroll
        for (int j = 0; j < 4; j++) o[a][j] = 0.0f;
    float m0 = -1e30f, m1 = -1e30f, l0 = 0.0f, l1 = 0.0f;

    const int r0g = row0 + warp * 16 + g;
    const int r1g = r0g + 8;

    const int ld_r  = tid >> 4;          // 0..7
    const int ld_c4 = tid & 15;          // 0..15

    // ---- preload tile 0 (64 keys) into stage 0 ----
    {
        const int key0 = chunk * 256;
        float4 t;
#pragma unroll
        for (int s = 0; s < 8; s++) {
            int r = ld_r + s * 8;
            t = *(const float4*)(Kp + (size_t)(key0 + r) * H_DIM + ld_c4 * 4);
            *(uint2*)&Ks[0][r][ld_c4 * 4] = make_uint2(h2u(t.x, t.y), h2u(t.z, t.w));
        }
#pragma unroll
        for (int s = 0; s < 8; s++) {
            int r = ld_r + s * 8;
            t = *(const float4*)(Vp + (size_t)(key0 + r) * H_DIM + ld_c4 * 4);
            Vt[0][ld_c4 * 4 + 0][r] = __float2half_rn(t.x);
            Vt[0][ld_c4 * 4 + 1][r] = __float2half_rn(t.y);
            Vt[0][ld_c4 * 4 + 2][r] = __float2half_rn(t.z);
            Vt[0][ld_c4 * 4 + 3][r] = __float2half_rn(t.w);
        }
    }

    for (int kb = 0; kb < nkt; kb++) {
        const int cur  = kb & 1;
        const int nxt  = 1 - cur;
        const int key0 = chunk * 256 + kb * 64;
        const bool more = (kb + 1 < nkt);
        __syncthreads();   // stage `cur` fully written; `nxt` readers done

        // prefetch next K (regs live only through S phase)
        float4 pk[8];
        if (more) {
            const int keyn = key0 + 64;
#pragma unroll
            for (int s = 0; s < 8; s++) {
                int r = ld_r + s * 8;
                pk[s] = *(const float4*)(Kp + (size_t)(keyn + r) * H_DIM + ld_c4 * 4);
            }
        }

        // ---- S = Q K^T : 8 atoms (64 keys) x 4 k-chunks of 16 ----
        float s[8][4];
#pragma unroll
        for (int a = 0; a < 8; a++)
#pragma unroll
            for (int j = 0; j < 4; j++) s[a][j] = 0.0f;

#pragma unroll
        for (int kc4 = 0; kc4 < 4; kc4++) {
            int kc = kc4 * 16;
#pragma unroll
            for (int at = 0; at < 8; at++) {
                unsigned b0 = ldu32(&Ks[cur][at * 8 + g][kc + 2 * tg    ]);
                unsigned b1 = ldu32(&Ks[cur][at * 8 + g][kc + 2 * tg + 8]);
                mma_f16(s[at], qa[kc4], b0, b1);
            }
        }

        // store next K into free stage; prefetch next V
        float4 pv[8];
        if (more) {
#pragma unroll
            for (int s2 = 0; s2 < 8; s2++) {
                int r = ld_r + s2 * 8;
                *(uint2*)&Ks[nxt][r][ld_c4 * 4] =
                    make_uint2(h2u(pk[s2].x, pk[s2].y), h2u(pk[s2].z, pk[s2].w));
            }
            const int keyn = key0 + 64;
#pragma unroll
            for (int s2 = 0; s2 < 8; s2++) {
                int r = ld_r + s2 * 8;
                pv[s2] = *(const float4*)(Vp + (size_t)(keyn + r) * H_DIM + ld_c4 * 4);
            }
        }

        // ---- scale + causal mask (diag tile is exactly key0 == row0) ----
        const bool diag = (key0 == row0);
#pragma unroll
        for (int at = 0; at < 8; at++) {
            s[at][0] *= 0.125f; s[at][1] *= 0.125f;
            s[at][2] *= 0.125f; s[at][3] *= 0.125f;
            if (diag) {
                int c0 = key0 + at * 8 + tg * 2;
                if (c0     > r0g) s[at][0] = -1e30f;
                if (c0 + 1 > r0g) s[at][1] = -1e30f;
                if (c0     > r1g) s[at][2] = -1e30f;
                if (c0 + 1 > r1g) s[at][3] = -1e30f;
            }
        }

        // ---- online softmax over 64 keys ----
        float tm0 = -1e30f, tm1 = -1e30f;
#pragma unroll
        for (int at = 0; at < 8; at++) {
            tm0 = fmaxf(tm0, fmaxf(s[at][0], s[at][1]));
            tm1 = fmaxf(tm1, fmaxf(s[at][2], s[at][3]));
        }
        tm0 = fmaxf(tm0, __shfl_xor_sync(0xffffffffu, tm0, 1));
        tm0 = fmaxf(tm0, __shfl_xor_sync(0xffffffffu, tm0, 2));
        tm1 = fmaxf(tm1, __shfl_xor_sync(0xffffffffu, tm1, 1));
        tm1 = fmaxf(tm1, __shfl_xor_sync(0xffffffffu, tm1, 2));

        float nm0 = fmaxf(m0, tm0), nm1 = fmaxf(m1, tm1);
        float al0 = __expf(m0 - nm0), al1 = __expf(m1 - nm1);
        m0 = nm0; m1 = nm1;

        float tl0 = 0.0f, tl1 = 0.0f;
#pragma unroll
        for (int at = 0; at < 8; at++) {
            s[at][0] = __expf(s[at][0] - nm0);
            s[at][1] = __expf(s[at][1] - nm0);
            s[at][2] = __expf(s[at][2] - nm1);
            s[at][3] = __expf(s[at][3] - nm1);
            tl0 += s[at][0] + s[at][1];
            tl1 += s[at][2] + s[at][3];
        }
        tl0 += __shfl_xor_sync(0xffffffffu, tl0, 1);
        tl0 += __shfl_xor_sync(0xffffffffu, tl0, 2);
        tl1 += __shfl_xor_sync(0xffffffffu, tl1, 1);
        tl1 += __shfl_xor_sync(0xffffffffu, tl1, 2);
        l0 = l0 * al0 + tl0;
        l1 = l1 * al1 + tl1;

#pragma unroll
        for (int at = 0; at < 8; at++) {
            o[at][0] *= al0; o[at][1] *= al0;
            o[at][2] *= al1; o[at][3] *= al1;
        }

        // stage P (warp-local rows)
#pragma unroll
        for (int at = 0; at < 8; at++) {
            int c = at * 8 + 2 * tg;
            *(unsigned*)&Ps[warp * 16 + g    ][c] = h2u(s[at][0], s[at][1]);
            *(unsigned*)&Ps[warp * 16 + g + 8][c] = h2u(s[at][2], s[at][3]);
        }
        __syncwarp();

        // ---- O += P V : 8 h-atoms x 4 key-chunks of 16 ----
#pragma unroll
        for (int kc = 0; kc < 64; kc += 16) {
            unsigned a[4];
            a[0] = ldu32(&Ps[warp * 16 + g    ][kc + 2 * tg    ]);
            a[1] = ldu32(&Ps[warp * 16 + g + 8][kc + 2 * tg    ]);
            a[2] = ldu32(&Ps[warp * 16 + g    ][kc + 2 * tg + 8]);
            a[3] = ldu32(&Ps[warp * 16 + g + 8][kc + 2 * tg + 8]);
#pragma unroll
            for (int at = 0; at < 8; at++) {
                unsigned b0 = ldu32(&Vt[cur][at * 8 + g][kc + 2 * tg    ]);
                unsigned b1 = ldu32(&Vt[cur][at * 8 + g][kc + 2 * tg + 8]);
                mma_f16(o[at], a, b0, b1);
            }
        }

        // store next V into free stage
        if (more) {
#pragma unroll
            for (int s2 = 0; s2 < 8; s2++) {
                int r = ld_r + s2 * 8;
                Vt[nxt][ld_c4 * 4 + 0][r] = __float2half_rn(pv[s2].x);
                Vt[nxt][ld_c4 * 4 + 1][r] = __float2half_rn(pv[s2].y);
                Vt[nxt][ld_c4 * 4 + 2][r] = __float2half_rn(pv[s2].z);
                Vt[nxt][ld_c4 * 4 + 3][r] = __float2half_rn(pv[s2].w);
            }
        }
    }

    // ---- write partial (unnormalized O, m, l) ----
    const size_t pidx = ((size_t)(b * QB_CNT + qb) * MAXCH + chunk);
    float* Op = g_Opart + pidx * 64 * 64;
    float* mlp = g_ml + pidx * 64 * 2;

    const int lr0 = warp * 16 + g;
#pragma unroll
    for (int at = 0; at < 8; at++) {
        int c = at * 8 + tg * 2;
        *(float2*)(Op + (size_t)lr0 * 64 + c)       = make_float2(o[at][0], o[at][1]);
        *(float2*)(Op + (size_t)(lr0 + 8) * 64 + c) = make_float2(o[at][2], o[at][3]);
    }
    if (tg == 0) {
        mlp[lr0 * 2 + 0] = m0;  mlp[lr0 * 2 + 1] = l0;
        mlp[(lr0 + 8) * 2 + 0] = m1;  mlp[(lr0 + 8) * 2 + 1] = l1;
    }
}

// ---------------------------------------------------------------------------
// Kernel 3: combine partials.  Block (64 rows, 16 col-segments of 4).
// ---------------------------------------------------------------------------
__global__ __launch_bounds__(1024) void combine_kernel(float* __restrict__ out)
{
    const int qb = blockIdx.x;
    const int b  = blockIdx.y;
    const int row = threadIdx.x;       // 0..63
    const int cs  = threadIdx.y;       // 0..15
    const int nc  = qb / 4 + 1;

    const size_t base = (size_t)(b * QB_CNT + qb) * MAXCH;

    __shared__ float wsm[MAXCH][64];
    __shared__ float Linv[64];

    if (cs == 0) {
        float M = -1e30f;
        for (int c = 0; c < nc; c++)
            M = fmaxf(M, g_ml[(base + c) * 128 + row * 2 + 0]);
        float L = 0.0f;
        for (int c = 0; c < nc; c++) {
            float m = g_ml[(base + c) * 128 + row * 2 + 0];
            float l = g_ml[(base + c) * 128 + row * 2 + 1];
            float w = __expf(m - M);
            wsm[c][row] = w;
            L += w * l;
        }
        Linv[row] = 1.0f / L;
    }
    __syncthreads();

    float acc0 = 0.f, acc1 = 0.f, acc2 = 0.f, acc3 = 0.f;
    const float* Ob = g_Opart + base * 4096 + (size_t)row * 64 + cs * 4;
#pragma unroll 4
    for (int c = 0; c < nc; c++) {
        float w = wsm[c][row];
        float4 v = *(const float4*)(Ob + (size_t)c * 4096);
        acc0 += w * v.x; acc1 += w * v.y; acc2 += w * v.z; acc3 += w * v.w;
    }

    float inv = Linv[row];
    float* op = out + (size_t)b * T_SEQ * H_DIM + (size_t)(qb * 64 + row) * H_DIM + cs * 4;
    *(float4*)op = make_float4(acc0 * inv, acc1 * inv, acc2 * inv, acc3 * inv);
}

// ---------------------------------------------------------------------------
extern "C" void kernel_launch(void* const* d_in, const int* in_sizes, int n_in,
                              void* d_out, int out_size)
{
    const float* x  = (const float*)d_in[0];
    const float* Wq = (const float*)d_in[1];
    const float* Wk = (const float*)d_in[2];
    const float* Wv = (const float*)d_in[3];
    float* out = (float*)d_out;

    zero_qkv<<<NROWS * H_DIM / 4 / 256, 256>>>();

    dim3 g1(NROWS / 128, KSPLIT, 3);
    proj_kernel<<<g1, 256>>>(x, Wq, Wk, Wv);

    dim3 g2(MAXCH, QB_CNT, B_BATCH);
    flash_part_kernel<<<g2, 128>>>();

    dim3 g3(QB_CNT, B_BATCH);
    combine_kernel<<<g3, dim3(64, 16)>>>(out);
}